// round 8
// baseline (speedup 1.0000x reference)
#include <cuda_runtime.h>
#include <cuda_bf16.h>
#include <cstdint>

// ---------------------------------------------------------------------------
// NCA step on tensor cores via warp-level mma.sync (bf16, f32 accum),
// split-bf16 for fp32 accuracy: v = hi(bf16) + lo(bf16),
// D = AhiBhi + AloBhi + AhiBlo  (lo*lo dropped, ~1e-5 rel err).
//   stage1: h = im2col(x)[128 px x 109] @ W1comb[109 x 96]   (bias as K-col)
//   stage2: upd = relu(h)[128 x 96] @ W2t[96 x 12]  + b2
//   out = x + upd * (mask > 0.5)
// Stage-2 A fragments are built DIRECTLY from stage-1 D fragments in
// registers (m16n8 D layout == m16k16 A layout after bf16 pair packing).
// ---------------------------------------------------------------------------

#define Bn   16
#define Cn   12
#define Hn   384
#define Wn   384
#define CPn  48
#define CHn  96
#define PIX  128

// SMEM layout (bytes)
#define SM_PATCH 0            // fp32 patch: 12*3*130 floats = 18720 B
#define SM_A     18944        // A hi panel: 128 rows x 240B = 30720
#define SM_ALO   49664        // A lo panel: 30720
#define SM_B1    80384        // B1t hi: 672 rows x 48B = 32256
#define SM_B1LO  112640       // B1t lo: 32256
#define SM_B2    144896       // B2t hi: 96 rows x 48B = 4608
#define SM_B2LO  149504       // B2t lo: 4608
#define SM_TOTAL 154112

#define ASTR 240              // A row stride (120 bf16; K 0..111 used)
#define BSTR 48               // Bt row stride (24 bf16; k16 used)

// Pre-swizzled weight images (written by fold kernel, copied to SMEM)
__device__ unsigned char g_B1img[64512];   // [hi 32256][lo 32256]
__device__ unsigned char g_B2img[9216];    // [hi 4608][lo 4608]

static __device__ __forceinline__ uint32_t smem_u32(const void* p) {
    uint32_t a;
    asm("{ .reg .u64 t; cvta.to.shared.u64 t, %1; cvt.u32.u64 %0, t; }"
        : "=r"(a) : "l"(p));
    return a;
}
static __device__ __forceinline__ void ldsm4(uint32_t* r, uint32_t addr) {
    asm volatile("ldmatrix.sync.aligned.m8n8.x4.shared.b16 {%0,%1,%2,%3}, [%4];"
        : "=r"(r[0]), "=r"(r[1]), "=r"(r[2]), "=r"(r[3]) : "r"(addr));
}
static __device__ __forceinline__ void mma16816(float* d, const uint32_t* a,
                                                uint32_t b0, uint32_t b1) {
    asm volatile(
        "mma.sync.aligned.m16n8k16.row.col.f32.bf16.bf16.f32 "
        "{%0,%1,%2,%3}, {%4,%5,%6,%7}, {%8,%9}, {%0,%1,%2,%3};"
        : "+f"(d[0]), "+f"(d[1]), "+f"(d[2]), "+f"(d[3])
        : "r"(a[0]), "r"(a[1]), "r"(a[2]), "r"(a[3]), "r"(b0), "r"(b1));
}
// pack two f32 -> bf16x2 reg (v0 in low half = even-k element)
static __device__ __forceinline__ uint32_t packbf(float v0, float v1) {
    uint32_t r;
    asm("cvt.rn.bf16x2.f32 %0, %1, %2;" : "=r"(r) : "f"(v1), "f"(v0));
    return r;
}
static __device__ __forceinline__ void split2(float v0, float v1,
                                              uint32_t& hi, uint32_t& lo) {
    __nv_bfloat16 h0 = __float2bfloat16(v0), h1 = __float2bfloat16(v1);
    float r0 = v0 - __bfloat162float(h0);
    float r1 = v1 - __bfloat162float(h1);
    __nv_bfloat162 hp; hp.x = h0; hp.y = h1;
    hi = *reinterpret_cast<uint32_t*>(&hp);
    lo = packbf(r0, r1);
}
static __device__ __forceinline__ void split2relu(float v0, float v1,
                                                  uint32_t& hi, uint32_t& lo) {
    split2(fmaxf(v0, 0.f), fmaxf(v1, 0.f), hi, lo);
}
static __device__ __forceinline__ float a_val(const float* pf, int px, int k) {
    if (k >= 108) return (k == 108) ? 1.f : 0.f;
    int c = k / 9, rem = k - c * 9;
    int dy = rem / 3, dx = rem - dy * 3;
    return pf[(c * 3 + dy) * 130 + px + dx];
}

// ---------------------------------------------------------------------------
// Fold: W1comb[k][o] = sum_p w1[o][p]*wperc[p][k]; images laid out as
// Bt[n][k] rows for direct ldmatrix: B1 row = (k>>4)*96 + o, B2 row =
// (j>>4)*16 + oc; 48B row stride; k-within-step at (k&15)*2.
// ---------------------------------------------------------------------------
__global__ void fold_kernel(const float* __restrict__ w1,
                            const float* __restrict__ wperc,
                            const float* __restrict__ b1,
                            const float* __restrict__ w2,
                            const float* __restrict__ b2) {
    int tid = threadIdx.x;   // 128 threads, 1 block
    for (int i = tid; i < 64512 / 4; i += 128) ((uint32_t*)g_B1img)[i] = 0;
    for (int i = tid; i < 9216 / 4;  i += 128) ((uint32_t*)g_B2img)[i] = 0;
    __syncthreads();
    if (tid < CHn) {
        int o = tid;
        for (int k = 0; k < 112; ++k) {
            float v = 0.f;
            if (k < 108) {
                for (int p = 0; p < CPn; ++p)
                    v = fmaf(w1[o * CPn + p], wperc[p * 108 + k], v);
            } else if (k == 108) v = b1[o];
            __nv_bfloat16 h = __float2bfloat16(v);
            float r = v - __bfloat162float(h);
            __nv_bfloat16 l = __float2bfloat16(r);
            int off = ((k >> 4) * 96 + o) * BSTR + (k & 15) * 2;
            *(uint16_t*)(g_B1img + off)         = *(uint16_t*)&h;
            *(uint16_t*)(g_B1img + 32256 + off) = *(uint16_t*)&l;
        }
    }
    if (tid < Cn) {
        int oc = tid;
        for (int j = 0; j < 96; ++j) {
            float v = w2[oc * CHn + j];
            __nv_bfloat16 h = __float2bfloat16(v);
            float r = v - __bfloat162float(h);
            __nv_bfloat16 l = __float2bfloat16(r);
            int off = ((j >> 4) * 16 + oc) * BSTR + (j & 15) * 2;
            *(uint16_t*)(g_B2img + off)        = *(uint16_t*)&h;
            *(uint16_t*)(g_B2img + 4608 + off) = *(uint16_t*)&l;
        }
    }
}

// ---------------------------------------------------------------------------
__global__ __launch_bounds__(256, 1)
void nca_mma(const float* __restrict__ x,
             const float* __restrict__ mask,
             const float* __restrict__ b2,
             float* __restrict__ out) {
    extern __shared__ char smc[];
    float* patchf = (float*)(smc + SM_PATCH);
    const uint32_t smb = smem_u32(smc);
    const int tid  = threadIdx.x;
    const int wid  = tid >> 5;
    const int lane = tid & 31;
    const int seg = blockIdx.x, gy = blockIdx.y, b = blockIdx.z;
    const int x0 = seg * PIX;

    // ---- load fp32 patch (wrap) -------------------------------------------
    const int ym1 = (gy == 0) ? (Hn - 1) : gy - 1;
    const int yp1 = (gy == Hn - 1) ? 0 : gy + 1;
    for (int idx = tid; idx < Cn * 3 * 130; idx += 256) {
        int col = idx % 130;
        int t = idx / 130;
        int r = t % 3, c = t / 3;
        int gyy = (r == 0) ? ym1 : (r == 1 ? gy : yp1);
        int gx = x0 + col - 1;
        gx = (gx < 0) ? gx + Wn : (gx >= Wn ? gx - Wn : gx);
        patchf[(c * 3 + r) * 130 + col] = x[((b * Cn + c) * Hn + gyy) * Wn + gx];
    }
    // ---- copy weight images -----------------------------------------------
    for (int i = tid; i < 64512 / 16; i += 256)
        ((uint4*)(smc + SM_B1))[i] = ((const uint4*)g_B1img)[i];
    for (int i = tid; i < 9216 / 16; i += 256)
        ((uint4*)(smc + SM_B2))[i] = ((const uint4*)g_B2img)[i];
    __syncthreads();

    // ---- build im2col A panels (hi/lo bf16) -------------------------------
    {
        int px = tid & 127;
        int half = tid >> 7;                 // k-range [half*56, half*56+56)
        char* Ah = smc + SM_A   + px * ASTR;
        char* Al = smc + SM_ALO + px * ASTR;
#pragma unroll 4
        for (int pr = 0; pr < 28; ++pr) {
            int k0 = half * 56 + 2 * pr;
            float v0 = a_val(patchf, px, k0);
            float v1 = a_val(patchf, px, k0 + 1);
            uint32_t hi, lo;
            split2(v0, v1, hi, lo);
            *(uint32_t*)(Ah + k0 * 2) = hi;
            *(uint32_t*)(Al + k0 * 2) = lo;
        }
    }
    __syncthreads();

    // ---- stage 1: warp m-stripes, 12 n-tiles, 7 k16-steps -----------------
    const int ws = wid * 16;
    float d[12][4];
#pragma unroll
    for (int i = 0; i < 12; ++i)
#pragma unroll
        for (int j = 0; j < 4; ++j) d[i][j] = 0.f;

    const uint32_t aRow = ws + (lane & 7) + ((lane >> 3) & 1) * 8;
    const uint32_t aK2  = ((lane >> 4) & 1) * 16;          // bytes
    const uint32_t addrA = smb + SM_A + aRow * ASTR + aK2;
    const uint32_t bN  = (lane & 7) + ((lane >> 4) & 1) * 8;
    const uint32_t bK2 = ((lane >> 3) & 1) * 16;           // bytes
    const uint32_t addrB = smb + SM_B1 + bN * BSTR + bK2;

#pragma unroll
    for (int s = 0; s < 7; ++s) {
        uint32_t ah[4], al[4];
        ldsm4(ah, addrA + s * 32);
        ldsm4(al, addrA + s * 32 + (SM_ALO - SM_A));
#pragma unroll
        for (int np = 0; np < 6; ++np) {
            uint32_t bh[4], bl[4];
            uint32_t ab = addrB + (s * 96 + np * 16) * BSTR;
            ldsm4(bh, ab);
            ldsm4(bl, ab + (SM_B1LO - SM_B1));
            mma16816(d[2 * np],     ah, bh[0], bh[1]);
            mma16816(d[2 * np + 1], ah, bh[2], bh[3]);
            mma16816(d[2 * np],     al, bh[0], bh[1]);
            mma16816(d[2 * np + 1], al, bh[2], bh[3]);
            mma16816(d[2 * np],     ah, bl[0], bl[1]);
            mma16816(d[2 * np + 1], ah, bl[2], bl[3]);
        }
    }

    // ---- stage 2: A2 frags straight from D1 frags (relu+split+pack) -------
    float e[2][4];
#pragma unroll
    for (int i = 0; i < 2; ++i)
#pragma unroll
        for (int j = 0; j < 4; ++j) e[i][j] = 0.f;

    const uint32_t addrB2 = smb + SM_B2 + bN * BSTR + bK2;
#pragma unroll
    for (int s = 0; s < 6; ++s) {
        uint32_t a2h[4], a2l[4];
        split2relu(d[2 * s][0],     d[2 * s][1],     a2h[0], a2l[0]);
        split2relu(d[2 * s][2],     d[2 * s][3],     a2h[1], a2l[1]);
        split2relu(d[2 * s + 1][0], d[2 * s + 1][1], a2h[2], a2l[2]);
        split2relu(d[2 * s + 1][2], d[2 * s + 1][3], a2h[3], a2l[3]);
        uint32_t bh[4], bl[4];
        uint32_t ab = addrB2 + s * 16 * BSTR;
        ldsm4(bh, ab);
        ldsm4(bl, ab + (SM_B2LO - SM_B2));
        mma16816(e[0], a2h, bh[0], bh[1]);
        mma16816(e[1], a2h, bh[2], bh[3]);
        mma16816(e[0], a2l, bh[0], bh[1]);
        mma16816(e[1], a2l, bh[2], bh[3]);
        mma16816(e[0], a2h, bl[0], bl[1]);
        mma16816(e[1], a2h, bl[2], bl[3]);
    }

    // ---- epilogue: out = x + (upd + b2) * (mask > 0.5) --------------------
    {
        int g = lane >> 2, t = lane & 3;
#pragma unroll
        for (int rr = 0; rr < 2; ++rr) {
            int px = ws + g + rr * 8;
            float m = (mask[gy * Wn + x0 + px] > 0.5f) ? 1.f : 0.f;
            size_t obase = ((size_t)(b * Cn) * Hn + gy) * Wn + x0 + px;
#pragma unroll
            for (int cc = 0; cc < 2; ++cc) {
                int oc = 2 * t + cc;
                float u = e[0][rr * 2 + cc] + __ldg(b2 + oc);
                float xc = patchf[(oc * 3 + 1) * 130 + px + 1];
                out[obase + (size_t)oc * Hn * Wn] = fmaf(u, m, xc);
            }
            if (t < 2) {
#pragma unroll
                for (int cc = 0; cc < 2; ++cc) {
                    int oc = 8 + 2 * t + cc;
                    float u = e[1][rr * 2 + cc] + __ldg(b2 + oc);
                    float xc = patchf[(oc * 3 + 1) * 130 + px + 1];
                    out[obase + (size_t)oc * Hn * Wn] = fmaf(u, m, xc);
                }
            }
        }
    }
}

// ---------------------------------------------------------------------------
extern "C" void kernel_launch(void* const* d_in, const int* in_sizes, int n_in,
                              void* d_out, int out_size) {
    const float* x      = (const float*)d_in[0];
    const float* w_perc = (const float*)d_in[1];
    const float* w1     = (const float*)d_in[2];
    const float* b1     = (const float*)d_in[3];
    const float* w2     = (const float*)d_in[4];
    const float* b2     = (const float*)d_in[5];
    const float* mask   = (const float*)d_in[6];
    float* out          = (float*)d_out;

    cudaFuncSetAttribute(nca_mma, cudaFuncAttributeMaxDynamicSharedMemorySize,
                         SM_TOTAL);

    fold_kernel<<<1, 128>>>(w1, w_perc, b1, w2, b2);
    dim3 grid(Wn / PIX, Hn, Bn);
    nca_mma<<<grid, 256, SM_TOTAL>>>(x, mask, b2, out);
}

// round 11
// speedup vs baseline: 1.7078x; 1.7078x over previous
#include <cuda_runtime.h>
#include <cuda_bf16.h>
#include <cstdint>

// ---------------------------------------------------------------------------
// NCA step on tensor cores via warp-level mma.sync (bf16, f32 accum),
// split-bf16 for fp32 accuracy: v = hi(bf16) + lo(bf16),
// D = AhiBhi + AloBhi + AhiBlo  (lo*lo dropped, ~2e-6 rel err measured).
//   stage1: h = im2col(x)[128 px x 109] @ W1comb[109 x 96]   (bias as K-col)
//   stage2: upd = relu(h)[128 x 96] @ W2t[96 x 12]  + b2
//   out = x + upd * (mask > 0.5)
// 2 CTAs/SM (smem 100.5KB via two-pass B1 + patch aliasing), fully-unrolled
// A build, round-robin MMA issue.
// ---------------------------------------------------------------------------

#define Bn   16
#define Cn   12
#define Hn   384
#define Wn   384
#define CPn  48
#define CHn  96
#define PIX  128

#define ASTR 240              // A row stride bytes (112 k-slots + pad)
#define BSTR 48               // Bt row stride bytes (16 k-slots + pad)

// SMEM layout (bytes)
#define SM_A     0            // A hi panel: 128 x 240 = 30720
#define SM_ALO   30720        // A lo panel: 30720
#define SM_B1    61440        // B1 buffer (hi, then lo): 672 x 48 = 32256
                              //   fp32 patch (18720 B) aliases here pre-MMA
#define SM_B2    93696        // B2t hi: 96 x 48 = 4608
#define SM_B2LO  98304        // B2t lo: 4608
#define SM_TOTAL 102912

// Weight images (written by fold kernel, copied to SMEM per block)
__device__ unsigned char g_B1img[64512];   // [hi 32256][lo 32256]
__device__ unsigned char g_B2img[9216];    // [hi 4608][lo 4608]

static __device__ __forceinline__ uint32_t smem_u32(const void* p) {
    uint32_t a;
    asm("{ .reg .u64 t; cvta.to.shared.u64 t, %1; cvt.u32.u64 %0, t; }"
        : "=r"(a) : "l"(p));
    return a;
}
static __device__ __forceinline__ void ldsm4(uint32_t* r, uint32_t addr) {
    asm volatile("ldmatrix.sync.aligned.m8n8.x4.shared.b16 {%0,%1,%2,%3}, [%4];"
        : "=r"(r[0]), "=r"(r[1]), "=r"(r[2]), "=r"(r[3]) : "r"(addr));
}
static __device__ __forceinline__ void mma16816(float* d, const uint32_t* a,
                                                uint32_t b0, uint32_t b1) {
    asm volatile(
        "mma.sync.aligned.m16n8k16.row.col.f32.bf16.bf16.f32 "
        "{%0,%1,%2,%3}, {%4,%5,%6,%7}, {%8,%9}, {%0,%1,%2,%3};"
        : "+f"(d[0]), "+f"(d[1]), "+f"(d[2]), "+f"(d[3])
        : "r"(a[0]), "r"(a[1]), "r"(a[2]), "r"(a[3]), "r"(b0), "r"(b1));
}
static __device__ __forceinline__ uint32_t packbf(float v0, float v1) {
    uint32_t r;
    asm("cvt.rn.bf16x2.f32 %0, %1, %2;" : "=r"(r) : "f"(v1), "f"(v0));
    return r;
}
static __device__ __forceinline__ void split2(float v0, float v1,
                                              uint32_t& hi, uint32_t& lo) {
    __nv_bfloat16 h0 = __float2bfloat16(v0), h1 = __float2bfloat16(v1);
    float r0 = v0 - __bfloat162float(h0);
    float r1 = v1 - __bfloat162float(h1);
    __nv_bfloat162 hp; hp.x = h0; hp.y = h1;
    hi = *reinterpret_cast<uint32_t*>(&hp);
    lo = packbf(r0, r1);
}
static __device__ __forceinline__ void split2relu(float v0, float v1,
                                                  uint32_t& hi, uint32_t& lo) {
    split2(fmaxf(v0, 0.f), fmaxf(v1, 0.f), hi, lo);
}
static __device__ __forceinline__ float a_val(const float* pf, int px, int k) {
    if (k >= 108) return (k == 108) ? 1.f : 0.f;
    int c = k / 9, rem = k - c * 9;
    int dy = rem / 3, dx = rem - dy * 3;
    return pf[(c * 3 + dy) * 130 + px + dx];
}

// Fully-unrolled A build for one k-half; KBASE compile-time so all index
// math (div/mod by 9/3) constant-folds.
template <int KBASE>
static __device__ __forceinline__ void buildA(const float* pf, int px,
                                              char* Ah, char* Al) {
#pragma unroll
    for (int pr = 0; pr < 28; ++pr) {
        const int k0 = KBASE + 2 * pr;
        float v0 = a_val(pf, px, k0);
        float v1 = a_val(pf, px, k0 + 1);
        uint32_t hi, lo;
        split2(v0, v1, hi, lo);
        *(uint32_t*)(Ah + k0 * 2) = hi;
        *(uint32_t*)(Al + k0 * 2) = lo;
    }
}

// ---------------------------------------------------------------------------
// Fold: W1comb[k][o] = sum_p w1[o][p]*wperc[p][k]; Bt[n][k] row layout:
// B1 row = (k>>4)*96 + o, B2 row = (j>>4)*16 + oc; 48B stride.
// ---------------------------------------------------------------------------
__global__ void fold_kernel(const float* __restrict__ w1,
                            const float* __restrict__ wperc,
                            const float* __restrict__ b1,
                            const float* __restrict__ w2,
                            const float* __restrict__ b2) {
    int tid = threadIdx.x;   // 128 threads, 1 block
    for (int i = tid; i < 64512 / 4; i += 128) ((uint32_t*)g_B1img)[i] = 0;
    for (int i = tid; i < 9216 / 4;  i += 128) ((uint32_t*)g_B2img)[i] = 0;
    __syncthreads();
    if (tid < CHn) {
        int o = tid;
        for (int k = 0; k < 112; ++k) {
            float v = 0.f;
            if (k < 108) {
                for (int p = 0; p < CPn; ++p)
                    v = fmaf(w1[o * CPn + p], wperc[p * 108 + k], v);
            } else if (k == 108) v = b1[o];
            __nv_bfloat16 h = __float2bfloat16(v);
            float r = v - __bfloat162float(h);
            __nv_bfloat16 l = __float2bfloat16(r);
            int off = ((k >> 4) * 96 + o) * BSTR + (k & 15) * 2;
            *(uint16_t*)(g_B1img + off)         = *(uint16_t*)&h;
            *(uint16_t*)(g_B1img + 32256 + off) = *(uint16_t*)&l;
        }
    }
    if (tid < Cn) {
        int oc = tid;
        for (int j = 0; j < 96; ++j) {
            float v = w2[oc * CHn + j];
            __nv_bfloat16 h = __float2bfloat16(v);
            float r = v - __bfloat162float(h);
            __nv_bfloat16 l = __float2bfloat16(r);
            int off = ((j >> 4) * 16 + oc) * BSTR + (j & 15) * 2;
            *(uint16_t*)(g_B2img + off)        = *(uint16_t*)&h;
            *(uint16_t*)(g_B2img + 4608 + off) = *(uint16_t*)&l;
        }
    }
}

// ---------------------------------------------------------------------------
__global__ __launch_bounds__(256, 2)
void nca_mma(const float* __restrict__ x,
             const float* __restrict__ mask,
             const float* __restrict__ b2,
             float* __restrict__ out) {
    extern __shared__ char smc[];
    float* patchf = (float*)(smc + SM_B1);       // aliases B1 buffer
    const uint32_t smb = smem_u32(smc);
    const int tid  = threadIdx.x;
    const int wid  = tid >> 5;
    const int lane = tid & 31;
    const int seg = blockIdx.x, gy = blockIdx.y, b = blockIdx.z;
    const int x0 = seg * PIX;

    // ---- phase 1: load fp32 patch (wrap) into B1 buffer region ------------
    const int ym1 = (gy == 0) ? (Hn - 1) : gy - 1;
    const int yp1 = (gy == Hn - 1) ? 0 : gy + 1;
    for (int idx = tid; idx < Cn * 3 * 130; idx += 256) {
        int col = idx % 130;
        int t = idx / 130;
        int r = t % 3, c = t / 3;
        int gyy = (r == 0) ? ym1 : (r == 1 ? gy : yp1);
        int gx = x0 + col - 1;
        gx = (gx < 0) ? gx + Wn : (gx >= Wn ? gx - Wn : gx);
        patchf[(c * 3 + r) * 130 + col] = x[((b * Cn + c) * Hn + gyy) * Wn + gx];
    }
    // B2 images (separate region, needed only in stage 2)
    for (int i = tid; i < 9216 / 16; i += 256)
        ((uint4*)(smc + SM_B2))[i] = ((const uint4*)g_B2img)[i];
    __syncthreads();

    // ---- phase 2: build im2col A panels (hi/lo bf16), fully unrolled ------
    {
        int px = tid & 127;
        char* Ah = smc + SM_A   + px * ASTR;
        char* Al = smc + SM_ALO + px * ASTR;
        if (tid < 128) buildA<0>(patchf, px, Ah, Al);
        else           buildA<56>(patchf, px, Ah, Al);
    }
    __syncthreads();

    // ---- phase 3: B1 hi image into B1 buffer (overwrites patch) -----------
    for (int i = tid; i < 32256 / 16; i += 256)
        ((uint4*)(smc + SM_B1))[i] = ((const uint4*)g_B1img)[i];
    __syncthreads();

    // ---- pass 1: D += Ahi*Bhi + Alo*Bhi -----------------------------------
    const int ws = wid * 16;
    float d[12][4];
#pragma unroll
    for (int i = 0; i < 12; ++i)
#pragma unroll
        for (int j = 0; j < 4; ++j) d[i][j] = 0.f;

    const uint32_t aRow = ws + (lane & 7) + ((lane >> 3) & 1) * 8;
    const uint32_t aK2  = ((lane >> 4) & 1) * 16;
    const uint32_t addrA  = smb + SM_A   + aRow * ASTR + aK2;
    const uint32_t addrAl = smb + SM_ALO + aRow * ASTR + aK2;
    const uint32_t bN  = (lane & 7) + ((lane >> 4) & 1) * 8;
    const uint32_t bK2 = ((lane >> 3) & 1) * 16;
    const uint32_t addrB = smb + SM_B1 + bN * BSTR + bK2;

#pragma unroll
    for (int s = 0; s < 7; ++s) {
        uint32_t ah[4], al[4], bh[6][4];
        ldsm4(ah, addrA  + s * 32);
        ldsm4(al, addrAl + s * 32);
#pragma unroll
        for (int np = 0; np < 6; ++np)
            ldsm4(bh[np], addrB + (s * 96 + np * 16) * BSTR);
        // round-robin across 12 independent d-tiles (chain spacing 12)
#pragma unroll
        for (int np = 0; np < 6; ++np) {
            mma16816(d[2 * np],     ah, bh[np][0], bh[np][1]);
            mma16816(d[2 * np + 1], ah, bh[np][2], bh[np][3]);
        }
#pragma unroll
        for (int np = 0; np < 6; ++np) {
            mma16816(d[2 * np],     al, bh[np][0], bh[np][1]);
            mma16816(d[2 * np + 1], al, bh[np][2], bh[np][3]);
        }
    }
    __syncthreads();

    // ---- phase 4: B1 lo image into B1 buffer ------------------------------
    for (int i = tid; i < 32256 / 16; i += 256)
        ((uint4*)(smc + SM_B1))[i] = ((const uint4*)(g_B1img + 32256))[i];
    __syncthreads();

    // ---- pass 2: D += Ahi*Blo ---------------------------------------------
#pragma unroll
    for (int s = 0; s < 7; ++s) {
        uint32_t ah[4], bl[6][4];
        ldsm4(ah, addrA + s * 32);
#pragma unroll
        for (int np = 0; np < 6; ++np)
            ldsm4(bl[np], addrB + (s * 96 + np * 16) * BSTR);
#pragma unroll
        for (int np = 0; np < 6; ++np) {
            mma16816(d[2 * np],     ah, bl[np][0], bl[np][1]);
            mma16816(d[2 * np + 1], ah, bl[np][2], bl[np][3]);
        }
    }

    // ---- stage 2: A2 frags straight from D1 frags (relu+split+pack) -------
    float e[2][4];
#pragma unroll
    for (int i = 0; i < 2; ++i)
#pragma unroll
        for (int j = 0; j < 4; ++j) e[i][j] = 0.f;

    const uint32_t addrB2 = smb + SM_B2 + bN * BSTR + bK2;
#pragma unroll
    for (int s = 0; s < 6; ++s) {
        uint32_t a2h[4], a2l[4];
        split2relu(d[2 * s][0],     d[2 * s][1],     a2h[0], a2l[0]);
        split2relu(d[2 * s][2],     d[2 * s][3],     a2h[1], a2l[1]);
        split2relu(d[2 * s + 1][0], d[2 * s + 1][1], a2h[2], a2l[2]);
        split2relu(d[2 * s + 1][2], d[2 * s + 1][3], a2h[3], a2l[3]);
        uint32_t bh[4], bl[4];
        uint32_t ab = addrB2 + s * 16 * BSTR;
        ldsm4(bh, ab);
        ldsm4(bl, ab + (SM_B2LO - SM_B2));
        mma16816(e[0], a2h, bh[0], bh[1]);
        mma16816(e[1], a2h, bh[2], bh[3]);
        mma16816(e[0], a2l, bh[0], bh[1]);
        mma16816(e[1], a2l, bh[2], bh[3]);
        mma16816(e[0], a2h, bl[0], bl[1]);
        mma16816(e[1], a2h, bl[2], bl[3]);
    }

    // ---- epilogue: out = x + (upd + b2) * (mask > 0.5); x via LDG ---------
    {
        int g = lane >> 2, t = lane & 3;
#pragma unroll
        for (int rr = 0; rr < 2; ++rr) {
            int px = ws + g + rr * 8;
            float m = (mask[gy * Wn + x0 + px] > 0.5f) ? 1.f : 0.f;
            size_t obase = ((size_t)(b * Cn) * Hn + gy) * Wn + x0 + px;
#pragma unroll
            for (int cc = 0; cc < 2; ++cc) {
                int oc = 2 * t + cc;
                float u = e[0][rr * 2 + cc] + __ldg(b2 + oc);
                float xc = __ldg(x + obase + (size_t)oc * Hn * Wn);
                out[obase + (size_t)oc * Hn * Wn] = fmaf(u, m, xc);
            }
            if (t < 2) {
#pragma unroll
                for (int cc = 0; cc < 2; ++cc) {
                    int oc = 8 + 2 * t + cc;
                    float u = e[1][rr * 2 + cc] + __ldg(b2 + oc);
                    float xc = __ldg(x + obase + (size_t)oc * Hn * Wn);
                    out[obase + (size_t)oc * Hn * Wn] = fmaf(u, m, xc);
                }
            }
        }
    }
}

// ---------------------------------------------------------------------------
extern "C" void kernel_launch(void* const* d_in, const int* in_sizes, int n_in,
                              void* d_out, int out_size) {
    const float* x      = (const float*)d_in[0];
    const float* w_perc = (const float*)d_in[1];
    const float* w1     = (const float*)d_in[2];
    const float* b1     = (const float*)d_in[3];
    const float* w2     = (const float*)d_in[4];
    const float* b2     = (const float*)d_in[5];
    const float* mask   = (const float*)d_in[6];
    float* out          = (float*)d_out;

    cudaFuncSetAttribute(nca_mma, cudaFuncAttributeMaxDynamicSharedMemorySize,
                         SM_TOTAL);

    fold_kernel<<<1, 128>>>(w1, w_perc, b1, w2, b2);
    dim3 grid(Wn / PIX, Hn, Bn);
    nca_mma<<<grid, 256, SM_TOTAL>>>(x, mask, b2, out);
}

// round 12
// speedup vs baseline: 2.4973x; 1.4622x over previous
#include <cuda_runtime.h>
#include <cuda_bf16.h>
#include <cstdint>

// ---------------------------------------------------------------------------
// NCA step, persistent-CTA tensor-core version (mma.sync bf16, f32 accum).
// split-bf16: v = hi + lo;  D = AhiBhi + AloBhi + AhiBlo  (~2e-6 rel err).
//   stage1: h = im2col(x)[128px x 109] @ W1comb[109 x 96]  (bias as K-col)
//   stage2: upd = relu(h) @ W2t[96 x 12] + b2
//   out = x + upd * (mask > 0.5)
// 148 persistent CTAs x 512 threads; ALL weights resident in SMEM for the
// CTA lifetime (no per-tile B copies, single MMA pass); patch LDG for the
// next tile prefetched into registers during the current tile's MMA.
// Warps: 8 m-stripes x 2 n-halves; stage-2 K-split partials summed via SMEM.
// ---------------------------------------------------------------------------

#define Bn   16
#define Cn   12
#define Hn   384
#define Wn   384
#define CPn  48
#define CHn  96
#define PIX  128
#define NT   (3 * Hn * Bn)     // 18432 tiles
#define NCTA 148
#define NTHR 512

#define ASTR 240               // A row stride bytes (112 k-slots + pad)
#define BSTR 48                // Bt row stride bytes (16 k-slots + pad)

// SMEM layout (bytes)
#define SM_A     0             // A hi: 128 x 240 = 30720
#define SM_ALO   30720         // A lo: 30720
#define SM_B1    61440         // B1t hi 32256, lo follows
#define SM_B1LO  93696
#define SM_B2    125952        // B2t hi 4608
#define SM_B2LO  130560
#define SM_UPD   135168        // partials: 2 x 128 x 16 f32 = 16384
#define SM_PATCH 151552        // fp32 patch: 4680 floats = 18720
#define SM_TOTAL 170272

// Weight images (written by fold kernel): [hi][lo] contiguous
__device__ unsigned char g_B1img[64512];
__device__ unsigned char g_B2img[9216];

static __device__ __forceinline__ uint32_t smem_u32(const void* p) {
    uint32_t a;
    asm("{ .reg .u64 t; cvta.to.shared.u64 t, %1; cvt.u32.u64 %0, t; }"
        : "=r"(a) : "l"(p));
    return a;
}
static __device__ __forceinline__ void ldsm4(uint32_t* r, uint32_t addr) {
    asm volatile("ldmatrix.sync.aligned.m8n8.x4.shared.b16 {%0,%1,%2,%3}, [%4];"
        : "=r"(r[0]), "=r"(r[1]), "=r"(r[2]), "=r"(r[3]) : "r"(addr));
}
static __device__ __forceinline__ void mma16816(float* d, const uint32_t* a,
                                                uint32_t b0, uint32_t b1) {
    asm volatile(
        "mma.sync.aligned.m16n8k16.row.col.f32.bf16.bf16.f32 "
        "{%0,%1,%2,%3}, {%4,%5,%6,%7}, {%8,%9}, {%0,%1,%2,%3};"
        : "+f"(d[0]), "+f"(d[1]), "+f"(d[2]), "+f"(d[3])
        : "r"(a[0]), "r"(a[1]), "r"(a[2]), "r"(a[3]), "r"(b0), "r"(b1));
}
static __device__ __forceinline__ uint32_t packbf(float v0, float v1) {
    uint32_t r;
    asm("cvt.rn.bf16x2.f32 %0, %1, %2;" : "=r"(r) : "f"(v1), "f"(v0));
    return r;
}
static __device__ __forceinline__ void split2(float v0, float v1,
                                              uint32_t& hi, uint32_t& lo) {
    __nv_bfloat16 h0 = __float2bfloat16(v0), h1 = __float2bfloat16(v1);
    float r0 = v0 - __bfloat162float(h0);
    float r1 = v1 - __bfloat162float(h1);
    __nv_bfloat162 hp; hp.x = h0; hp.y = h1;
    hi = *reinterpret_cast<uint32_t*>(&hp);
    lo = packbf(r0, r1);
}
static __device__ __forceinline__ void split2relu(float v0, float v1,
                                                  uint32_t& hi, uint32_t& lo) {
    split2(fmaxf(v0, 0.f), fmaxf(v1, 0.f), hi, lo);
}
static __device__ __forceinline__ float a_val(const float* pf, int px, int k) {
    if (k >= 108) return (k == 108) ? 1.f : 0.f;
    int c = k / 9, rem = k - c * 9;
    int dy = rem / 3, dx = rem - dy * 3;
    return pf[(c * 3 + dy) * 130 + px + dx];
}

// Fully-unrolled A build for one k-quarter (28 slots = 14 pairs); KBASE
// compile-time so the /9 and /3 index math constant-folds.
template <int KBASE>
static __device__ __forceinline__ void buildA(const float* pf, int px,
                                              char* Ah, char* Al) {
#pragma unroll
    for (int pr = 0; pr < 14; ++pr) {
        const int k0 = KBASE + 2 * pr;
        float v0 = a_val(pf, px, k0);
        float v1 = a_val(pf, px, k0 + 1);
        uint32_t hi, lo;
        split2(v0, v1, hi, lo);
        *(uint32_t*)(Ah + k0 * 2) = hi;
        *(uint32_t*)(Al + k0 * 2) = lo;
    }
}

// ---------------------------------------------------------------------------
// Fold: W1comb[k][o] = sum_p w1[o][p]*wperc[p][k]; Bt[n][k] row layout:
// B1 row = (k>>4)*96 + o, B2 row = (j>>4)*16 + oc; 48B stride.
// ---------------------------------------------------------------------------
__global__ void fold_kernel(const float* __restrict__ w1,
                            const float* __restrict__ wperc,
                            const float* __restrict__ b1,
                            const float* __restrict__ w2,
                            const float* __restrict__ b2) {
    int tid = threadIdx.x;
    for (int i = tid; i < 64512 / 4; i += 128) ((uint32_t*)g_B1img)[i] = 0;
    for (int i = tid; i < 9216 / 4;  i += 128) ((uint32_t*)g_B2img)[i] = 0;
    __syncthreads();
    if (tid < CHn) {
        int o = tid;
        for (int k = 0; k < 112; ++k) {
            float v = 0.f;
            if (k < 108) {
                for (int p = 0; p < CPn; ++p)
                    v = fmaf(w1[o * CPn + p], wperc[p * 108 + k], v);
            } else if (k == 108) v = b1[o];
            __nv_bfloat16 h = __float2bfloat16(v);
            float r = v - __bfloat162float(h);
            __nv_bfloat16 l = __float2bfloat16(r);
            int off = ((k >> 4) * 96 + o) * BSTR + (k & 15) * 2;
            *(uint16_t*)(g_B1img + off)         = *(uint16_t*)&h;
            *(uint16_t*)(g_B1img + 32256 + off) = *(uint16_t*)&l;
        }
    }
    if (tid < Cn) {
        int oc = tid;
        for (int j = 0; j < 96; ++j) {
            float v = w2[oc * CHn + j];
            __nv_bfloat16 h = __float2bfloat16(v);
            float r = v - __bfloat162float(h);
            __nv_bfloat16 l = __float2bfloat16(r);
            int off = ((j >> 4) * 16 + oc) * BSTR + (j & 15) * 2;
            *(uint16_t*)(g_B2img + off)        = *(uint16_t*)&h;
            *(uint16_t*)(g_B2img + 4608 + off) = *(uint16_t*)&l;
        }
    }
}

// prefetch patch for tile into registers (wrap padding applied)
static __device__ __forceinline__ void prefetch_patch(
    const float* __restrict__ x, int tile, int tid, float* pf) {
    int seg = tile % 3;
    int t1  = tile / 3;
    int gy  = t1 % Hn;
    int b   = t1 / Hn;
    int x0  = seg * PIX;
    int ym1 = (gy == 0) ? (Hn - 1) : gy - 1;
    int yp1 = (gy == Hn - 1) ? 0 : gy + 1;
#pragma unroll
    for (int j = 0; j < 10; ++j) {
        int idx = tid + j * NTHR;
        if (idx < Cn * 3 * 130) {
            int col = idx % 130;
            int t = idx / 130;
            int r = t % 3, c = t / 3;
            int gyy = (r == 0) ? ym1 : (r == 1 ? gy : yp1);
            int gx = x0 + col - 1;
            gx = (gx < 0) ? gx + Wn : (gx >= Wn ? gx - Wn : gx);
            pf[j] = __ldg(x + ((size_t)(b * Cn + c) * Hn + gyy) * Wn + gx);
        }
    }
}

// ---------------------------------------------------------------------------
__global__ __launch_bounds__(NTHR, 1)
void nca_mma(const float* __restrict__ x,
             const float* __restrict__ mask,
             const float* __restrict__ b2,
             float* __restrict__ out) {
    extern __shared__ char smc[];
    float* patchf = (float*)(smc + SM_PATCH);
    float* updp   = (float*)(smc + SM_UPD);
    const uint32_t smb = smem_u32(smc);
    const int tid  = threadIdx.x;
    const int wid  = tid >> 5;
    const int lane = tid & 31;
    const int hf   = wid & 1;          // n-half (stage1) = k-half (stage2)
    const int ws   = (wid >> 1) * 16;  // m-stripe

    // ---- load ALL weights into SMEM once ----------------------------------
    for (int i = tid; i < 64512 / 16; i += NTHR)
        ((uint4*)(smc + SM_B1))[i] = ((const uint4*)g_B1img)[i];
    for (int i = tid; i < 9216 / 16; i += NTHR)
        ((uint4*)(smc + SM_B2))[i] = ((const uint4*)g_B2img)[i];

    // loop-invariant fragment addresses
    const uint32_t aRow = ws + (lane & 7) + ((lane >> 3) & 1) * 8;
    const uint32_t aK2  = ((lane >> 4) & 1) * 16;
    const uint32_t addrA  = smb + SM_A   + aRow * ASTR + aK2;
    const uint32_t addrAl = smb + SM_ALO + aRow * ASTR + aK2;
    const uint32_t bN  = (lane & 7) + ((lane >> 4) & 1) * 8;
    const uint32_t bK2 = ((lane >> 3) & 1) * 16;
    const uint32_t addrB1 = smb + SM_B1 + (hf * 48 + bN) * BSTR + bK2;
    const uint32_t addrB2 = smb + SM_B2 + bN * BSTR + bK2;

    const int px128 = tid & 127;
    const int q     = tid >> 7;
    char* Ah = smc + SM_A   + px128 * ASTR;
    char* Al = smc + SM_ALO + px128 * ASTR;

    float pf[10];
    int tile = blockIdx.x;
    prefetch_patch(x, tile, tid, pf);

    for (; tile < NT; tile += NCTA) {
        const int seg = tile % 3;
        const int t1  = tile / 3;
        const int gy  = t1 % Hn;
        const int b   = t1 / Hn;
        const int x0  = seg * PIX;

        // ---- commit prefetched patch to SMEM ------------------------------
#pragma unroll
        for (int j = 0; j < 10; ++j) {
            int idx = tid + j * NTHR;
            if (idx < Cn * 3 * 130) patchf[idx] = pf[j];
        }
        __syncthreads();                                   // sync1

        // ---- build im2col A panels (one k-quarter per thread group) -------
        if      (q == 0) buildA<0>(patchf, px128, Ah, Al);
        else if (q == 1) buildA<28>(patchf, px128, Ah, Al);
        else if (q == 2) buildA<56>(patchf, px128, Ah, Al);
        else             buildA<84>(patchf, px128, Ah, Al);
        __syncthreads();                                   // sync2

        // ---- prefetch next tile's patch (lands during MMA) ----------------
        int ntile = tile + NCTA;
        if (ntile < NT) prefetch_patch(x, ntile, tid, pf);

        // ---- stage 1: single pass, 3 chains, warp n-half ------------------
        float d[6][4];
#pragma unroll
        for (int i = 0; i < 6; ++i)
#pragma unroll
            for (int j = 0; j < 4; ++j) d[i][j] = 0.f;

#pragma unroll
        for (int s = 0; s < 7; ++s) {
            uint32_t ah[4], al[4], bh[3][4], bl[3][4];
            ldsm4(ah, addrA  + s * 32);
            ldsm4(al, addrAl + s * 32);
#pragma unroll
            for (int np = 0; np < 3; ++np) {
                uint32_t ab = addrB1 + (s * 96 + np * 16) * BSTR;
                ldsm4(bh[np], ab);
                ldsm4(bl[np], ab + (SM_B1LO - SM_B1));
            }
#pragma unroll
            for (int np = 0; np < 3; ++np) {
                mma16816(d[2 * np],     ah, bh[np][0], bh[np][1]);
                mma16816(d[2 * np + 1], ah, bh[np][2], bh[np][3]);
            }
#pragma unroll
            for (int np = 0; np < 3; ++np) {
                mma16816(d[2 * np],     al, bh[np][0], bh[np][1]);
                mma16816(d[2 * np + 1], al, bh[np][2], bh[np][3]);
            }
#pragma unroll
            for (int np = 0; np < 3; ++np) {
                mma16816(d[2 * np],     ah, bl[np][0], bl[np][1]);
                mma16816(d[2 * np + 1], ah, bl[np][2], bl[np][3]);
            }
        }

        // ---- stage 2: A2 frags from D1 frags; warp owns 3 k-tiles ---------
        float e[2][4];
#pragma unroll
        for (int i = 0; i < 2; ++i)
#pragma unroll
            for (int j = 0; j < 4; ++j) e[i][j] = 0.f;

#pragma unroll
        for (int j = 0; j < 3; ++j) {
            uint32_t a2h[4], a2l[4];
            split2relu(d[2 * j][0],     d[2 * j][1],     a2h[0], a2l[0]);
            split2relu(d[2 * j][2],     d[2 * j][3],     a2h[1], a2l[1]);
            split2relu(d[2 * j + 1][0], d[2 * j + 1][1], a2h[2], a2l[2]);
            split2relu(d[2 * j + 1][2], d[2 * j + 1][3], a2h[3], a2l[3]);
            int s2 = hf * 3 + j;
            uint32_t bh[4], bl[4];
            uint32_t ab = addrB2 + s2 * 16 * BSTR;
            ldsm4(bh, ab);
            ldsm4(bl, ab + (SM_B2LO - SM_B2));
            mma16816(e[0], a2h, bh[0], bh[1]);
            mma16816(e[1], a2h, bh[2], bh[3]);
            mma16816(e[0], a2l, bh[0], bh[1]);
            mma16816(e[1], a2l, bh[2], bh[3]);
            mma16816(e[0], a2h, bl[0], bl[1]);
            mma16816(e[1], a2h, bl[2], bl[3]);
        }

        // ---- store stage-2 partial sums (per k-half) ----------------------
        {
            int g = lane >> 2, t = lane & 3;
            float* up = updp + hf * 2048;
#pragma unroll
            for (int rr = 0; rr < 2; ++rr) {
                int px = ws + g + rr * 8;
#pragma unroll
                for (int cc = 0; cc < 2; ++cc)
                    up[px * 16 + 2 * t + cc] = e[0][rr * 2 + cc];
                if (t < 2) {
#pragma unroll
                    for (int cc = 0; cc < 2; ++cc)
                        up[px * 16 + 8 + 2 * t + cc] = e[1][rr * 2 + cc];
                }
            }
        }
        __syncthreads();                                   // sync3

        // ---- epilogue: out = x + (upd0+upd1+b2) * (mask>0.5) --------------
        {
            int px = tid & 127;
            float m = (mask[gy * Wn + x0 + px] > 0.5f) ? 1.f : 0.f;
#pragma unroll
            for (int k = 0; k < 3; ++k) {
                int oc = (tid >> 7) + 4 * k;
                float u = updp[px * 16 + oc] + updp[2048 + px * 16 + oc] +
                          __ldg(b2 + oc);
                size_t off = ((size_t)(b * Cn + oc) * Hn + gy) * Wn + x0 + px;
                out[off] = fmaf(u, m, __ldg(x + off));
            }
        }
        __syncthreads();                                   // sync4 (upd reuse)
    }
}

// ---------------------------------------------------------------------------
extern "C" void kernel_launch(void* const* d_in, const int* in_sizes, int n_in,
                              void* d_out, int out_size) {
    const float* x      = (const float*)d_in[0];
    const float* w_perc = (const float*)d_in[1];
    const float* w1     = (const float*)d_in[2];
    const float* b1     = (const float*)d_in[3];
    const float* w2     = (const float*)d_in[4];
    const float* b2     = (const float*)d_in[5];
    const float* mask   = (const float*)d_in[6];
    float* out          = (float*)d_out;

    cudaFuncSetAttribute(nca_mma, cudaFuncAttributeMaxDynamicSharedMemorySize,
                         SM_TOTAL);

    fold_kernel<<<1, 128>>>(w1, w_perc, b1, w2, b2);
    nca_mma<<<NCTA, NTHR, SM_TOTAL>>>(x, mask, b2, out);
}